// round 2
// baseline (speedup 1.0000x reference)
#include <cuda_runtime.h>

#define BATCH 8192
#define CLS   32000
#define NTHREADS 256

// Per-row loss scratch (no device allocation allowed in kernel_launch).
__device__ float g_row_loss[BATCH];

__global__ __launch_bounds__(NTHREADS) void supcon_row_kernel(
    const float* __restrict__ y_pred,
    const int* __restrict__ y_true)   // labels are int32 (JAX x64 disabled demotes int64)
{
    const int row = blockIdx.x;
    const int tid = threadIdx.x;
    const float4* __restrict__ p =
        reinterpret_cast<const float4*>(y_pred + (size_t)row * CLS);

    // 4 independent accumulators: breaks the FADD RAW chain (lat 4),
    // keeps the loop bound by LDG issue, not FP latency.
    float s0 = 0.f, s1 = 0.f, s2 = 0.f, s3 = 0.f;

    constexpr int NV = CLS / 4;  // 8000 float4 per row
    #pragma unroll 4
    for (int i = tid; i < NV; i += NTHREADS) {
        float4 v = p[i];
        s0 += __expf(v.x);
        s1 += __expf(v.y);
        s2 += __expf(v.z);
        s3 += __expf(v.w);
    }
    float s = (s0 + s1) + (s2 + s3);

    // Block reduction: warp shuffle + smem across 8 warps.
    __shared__ float red[NTHREADS / 32];
    #pragma unroll
    for (int off = 16; off > 0; off >>= 1)
        s += __shfl_down_sync(0xffffffffu, s, off);
    if ((tid & 31) == 0) red[tid >> 5] = s;
    __syncthreads();

    if (tid < (NTHREADS / 32)) {
        s = red[tid];
        #pragma unroll
        for (int off = (NTHREADS / 64); off > 0; off >>= 1)
            s += __shfl_down_sync(0xffu, s, off);
        if (tid == 0) {
            const int t = y_true[row];
            const float yt = y_pred[(size_t)row * CLS + (size_t)t];
            // Same __expf bits as accumulated above -> exact cancellation.
            const float sum_neg = s - __expf(yt);
            g_row_loss[row] = log1pf(sum_neg * expf(-yt));
        }
    }
}

__global__ __launch_bounds__(NTHREADS) void supcon_final_kernel(float* __restrict__ out)
{
    const int tid = threadIdx.x;
    float s = 0.f;
    #pragma unroll 8
    for (int i = tid; i < BATCH; i += NTHREADS)
        s += g_row_loss[i];

    __shared__ float red[NTHREADS / 32];
    #pragma unroll
    for (int off = 16; off > 0; off >>= 1)
        s += __shfl_down_sync(0xffffffffu, s, off);
    if ((tid & 31) == 0) red[tid >> 5] = s;
    __syncthreads();

    if (tid < (NTHREADS / 32)) {
        s = red[tid];
        #pragma unroll
        for (int off = (NTHREADS / 64); off > 0; off >>= 1)
            s += __shfl_down_sync(0xffu, s, off);
        if (tid == 0) out[0] = s * (1.0f / (float)BATCH);
    }
}

extern "C" void kernel_launch(void* const* d_in, const int* in_sizes, int n_in,
                              void* d_out, int out_size)
{
    const float* y_pred = (const float*)d_in[0];
    const int* y_true = (const int*)d_in[1];
    float* out = (float*)d_out;

    supcon_row_kernel<<<BATCH, NTHREADS>>>(y_pred, y_true);
    supcon_final_kernel<<<1, NTHREADS>>>(out);
}

// round 4
// speedup vs baseline: 1.0282x; 1.0282x over previous
#include <cuda_runtime.h>

#define BATCH 8192
#define CLS   32000
#define NTHREADS 256

__global__ __launch_bounds__(NTHREADS) void supcon_fused_kernel(
    const float* __restrict__ y_pred,
    const int* __restrict__ y_true,   // labels are int32 (JAX x64-disabled demotes int64)
    float* __restrict__ out)
{
    const int row = blockIdx.x;
    const int tid = threadIdx.x;
    const float4* __restrict__ p =
        reinterpret_cast<const float4*>(y_pred + (size_t)row * CLS);

    // Prefetch label + target logit on thread 0 BEFORE the streaming loop so the
    // dependent gather chain (~2x L2/DRAM latency) hides under the 8000-iter stream.
    float yt = 0.f;
    if (tid == 0) {
        const int t = y_true[row];
        yt = y_pred[(size_t)row * CLS + (size_t)t];
    }

    // 4 independent accumulators: breaks the FADD RAW chain (lat 4),
    // keeps the loop bound by LDG issue, not FP latency.
    float s0 = 0.f, s1 = 0.f, s2 = 0.f, s3 = 0.f;

    constexpr int NV = CLS / 4;  // 8000 float4 per row
    #pragma unroll 4
    for (int i = tid; i < NV; i += NTHREADS) {
        float4 v = p[i];
        s0 += __expf(v.x);
        s1 += __expf(v.y);
        s2 += __expf(v.z);
        s3 += __expf(v.w);
    }
    float s = (s0 + s1) + (s2 + s3);

    // Block reduction: warp shuffle + smem across 8 warps.
    __shared__ float red[NTHREADS / 32];
    #pragma unroll
    for (int off = 16; off > 0; off >>= 1)
        s += __shfl_down_sync(0xffffffffu, s, off);
    if ((tid & 31) == 0) red[tid >> 5] = s;
    __syncthreads();

    if (tid == 0) {
        #pragma unroll
        for (int w = 1; w < NTHREADS / 32; w++)
            s += red[w];
        // e = exp(yt) with the same __expf bits as accumulated in the stream:
        // (s - e) cancels the positive term exactly; dividing by e replaces a
        // second MUFU exp on the dependent tail.
        const float e = __expf(yt);
        const float loss = log1pf((s - e) / e);
        // Mean fused via global atomic; d_out zeroed by memset node in kernel_launch.
        atomicAdd(out, loss * (1.0f / (float)BATCH));
    }
}

extern "C" void kernel_launch(void* const* d_in, const int* in_sizes, int n_in,
                              void* d_out, int out_size)
{
    const float* y_pred = (const float*)d_in[0];
    const int* y_true = (const int*)d_in[1];
    float* out = (float*)d_out;

    // d_out is poisoned (0xAA) before timing; zero it every call so the graph
    // replay is self-contained. Memset nodes are graph-capturable.
    cudaMemsetAsync(out, 0, sizeof(float));
    supcon_fused_kernel<<<BATCH, NTHREADS>>>(y_pred, y_true, out);
}